// round 14
// baseline (speedup 1.0000x reference)
#include <cuda_runtime.h>

// Single-layer LSTM, T=4096, B=1024, I=H=4, seq-first, zero init state.
// 4 lanes per batch element; 128 blocks x 32 threads -> 1 warp per SM.
//
// R11: measured MUFU effective chain latency ~70 cyc (solved from R1 vs R2
// timings). The two on-chain tanh links dominate the 215-cyc step. Replace
// the chain-critical activations (f,i,g gates and tanh(c)) with an
// FFMA-pipe-only rational:
//   tanh(x) ~= x*(135135+17325u+378u^2+u^3)/(135135+62370u+3150u^2+28u^3),
//   u = x^2, input clamped to [-5,5]   (Pade[7/6] via continued fraction;
//   err <= ~1e-4 incl. clamp tail)
// with the division done by magic-constant reciprocal seed + 2 Newton steps
// (no MUFU anywhere on the chain; clamp/magic ride the alu pipe).
// The o-gate keeps MUFU.TANH: its latency is hidden (needed ~108 cyc later).
// Sigmoid rows pre-scaled 0.5 (sigmoid(x) = 0.5 + 0.5*tanh(x/2)).

#define TLEN   4096
#define BATCH  1024
#define OUTSTRIDE (BATCH * 4)
#define UNROLL 8

typedef unsigned long long u64;

__device__ __forceinline__ float tanhf_a(float x) {
    float y; asm("tanh.approx.f32 %0, %1;" : "=f"(y) : "f"(x)); return y;
}
__device__ __forceinline__ u64 pack2(float lo, float hi) {
    u64 r; asm("mov.b64 %0, {%1, %2};" : "=l"(r) : "f"(lo), "f"(hi)); return r;
}
__device__ __forceinline__ void unpack2(float& lo, float& hi, u64 v) {
    asm("mov.b64 {%0, %1}, %2;" : "=f"(lo), "=f"(hi) : "l"(v));
}
__device__ __forceinline__ u64 fma2(u64 a, u64 b, u64 c) {
    u64 r; asm("fma.rn.f32x2 %0, %1, %2, %3;" : "=l"(r) : "l"(a), "l"(b), "l"(c)); return r;
}
__device__ __forceinline__ float shfl_bfly(float v, int m) {
    float y;
    asm volatile("shfl.sync.bfly.b32 %0, %1, %2, 0x1f, 0xffffffff;"
                 : "=f"(y) : "f"(v), "r"(m));
    return y;
}

// FFMA-pipe tanh: Pade[7/6], clamp +-5, magic-seed reciprocal + 2 Newton.
// Chain ~50 cyc, 13 fma-pipe ops + 3 alu-pipe ops. No MUFU.
__device__ __forceinline__ float rat_tanh(float x) {
    x = fminf(5.0f, fmaxf(-5.0f, x));            // alu pipe (FMNMX)
    const float u = x * x;
    // Numerator: ((u+378)u+17325)u+135135, times x.
    float n = u + 378.0f;
    n = fmaf(n, u, 17325.0f);
    n = fmaf(n, u, 135135.0f);
    const float xn = x * n;
    // Denominator: ((28u+3150)u+62370)u+135135  (always >= 135135 > 0).
    float d = fmaf(28.0f, u, 3150.0f);
    d = fmaf(d, u, 62370.0f);
    d = fmaf(d, u, 135135.0f);
    // 1/d: magic seed (~5% err) + 2 Newton iterations (-> ~1e-4).
    float y = __int_as_float(0x7EF311C3 - __float_as_int(d));  // alu pipe
    y = y * fmaf(-d, y, 2.0f);
    y = y * fmaf(-d, y, 2.0f);
    return xn * y;
}

__global__ void __launch_bounds__(32, 1)
lstm_recur(const float* __restrict__ input,
           const float* __restrict__ W_ih,
           const float* __restrict__ W_hh,
           const float* __restrict__ b_ih,
           const float* __restrict__ b_hh,
           float* __restrict__ out)
{
    const int g = blockIdx.x * 32 + threadIdx.x;   // 0..4095
    const int b = g >> 2;                          // batch element
    const int j = g & 3;                           // hidden unit owned by lane

    // PyTorch gate rows for unit j: i=j, f=4+j, g=8+j, o=12+j.
    // Pack A = (i, f) pre-scaled 0.5; pack B = (g, o) scaled (1.0, 0.5).
    // W_hh columns xor-permuted: shfl_xor(h, m) multiplies column (j^m).
    const int ri = j, rf = 4 + j, rg = 8 + j, ro = 12 + j;
    u64 wA[4], wB[4], uA[4], uB[4];
#pragma unroll
    for (int m = 0; m < 4; ++m) {
        wA[m] = pack2(W_ih[ri * 4 + m] * 0.5f, W_ih[rf * 4 + m] * 0.5f);
        wB[m] = pack2(W_ih[rg * 4 + m],        W_ih[ro * 4 + m] * 0.5f);
        const int mc = j ^ m;
        uA[m] = pack2(W_hh[ri * 4 + mc] * 0.5f, W_hh[rf * 4 + mc] * 0.5f);
        uB[m] = pack2(W_hh[rg * 4 + mc],        W_hh[ro * 4 + mc] * 0.5f);
    }
    const u64 biasA = pack2((b_ih[ri] + b_hh[ri]) * 0.5f,
                            (b_ih[rf] + b_hh[rf]) * 0.5f);
    const u64 biasB = pack2((b_ih[rg] + b_hh[rg]),
                            (b_ih[ro] + b_hh[ro]) * 0.5f);

    const float4* __restrict__ xin = reinterpret_cast<const float4*>(input) + b;

    // 8-deep software prefetch (double buffer): covers 577-cyc DRAM latency.
    float4 xbuf[UNROLL], xnxt[UNROLL];
#pragma unroll
    for (int u = 0; u < UNROLL; ++u) xbuf[u] = xin[u * BATCH];

    float h = 0.0f, c = 0.0f;
    float* op = out + g;

#pragma unroll 1
    for (int t0 = 0; t0 < TLEN; t0 += UNROLL) {
#pragma unroll
        for (int u = 0; u < UNROLL; ++u) {
            int tp = t0 + UNROLL + u;
            tp = (tp < TLEN) ? tp : (TLEN - 1);
            xnxt[u] = xin[tp * BATCH];
        }

#pragma unroll
        for (int u = 0; u < UNROLL; ++u) {
            // ---- Input projection, packed (off the serial chain). ----
            const u64 x0p = pack2(xbuf[u].x, xbuf[u].x);
            const u64 x1p = pack2(xbuf[u].y, xbuf[u].y);
            const u64 x2p = pack2(xbuf[u].z, xbuf[u].z);
            const u64 x3p = pack2(xbuf[u].w, xbuf[u].w);

            u64 pA = fma2(x0p, wA[0], biasA);
            u64 pB = fma2(x0p, wB[0], biasB);
            pA = fma2(x1p, wA[1], pA);
            pB = fma2(x1p, wB[1], pB);
            pA = fma2(x2p, wA[2], pA);
            pB = fma2(x2p, wB[2], pB);
            pA = fma2(x3p, wA[3], pA);
            pB = fma2(x3p, wB[3], pB);

            // ---- Exchange hidden state (3 shfls; h from previous step). ----
            const float h1 = shfl_bfly(h, 1);
            const float h2 = shfl_bfly(h, 2);
            const float h3 = shfl_bfly(h, 3);

            const u64 h0p = pack2(h, h);          // starts before shfls land
            u64 aA = fma2(h0p, uA[0], pA);
            u64 aB = fma2(h0p, uB[0], pB);

            const u64 h1p = pack2(h1, h1);
            const u64 h2p = pack2(h2, h2);
            const u64 h3p = pack2(h3, h3);
            aA = fma2(h1p, uA[1], aA);
            aB = fma2(h1p, uB[1], aB);
            aA = fma2(h2p, uA[2], aA);
            aB = fma2(h2p, uB[2], aB);
            aA = fma2(h3p, uA[3], aA);
            aB = fma2(h3p, uB[3], aB);

            // ---- Activations. Chain-critical (f,i,g,c): FFMA rational.
            //      Off-chain (o): MUFU.TANH, latency hidden. ----
            float ai, af, ag, ao;
            unpack2(ai, af, aA);
            unpack2(ag, ao, aB);

            const float to = tanhf_a(ao);         // issue first: 70-cyc shadow

            const float tf = rat_tanh(af);
            const float ti = rat_tanh(ai);
            const float tg = rat_tanh(ag);

            const float sf = fmaf(tf, 0.5f, 0.5f);
            const float si = fmaf(ti, 0.5f, 0.5f);

            // ---- Cell update and h output. ----
            c = fmaf(si, tg, sf * c);
            const float tc = rat_tanh(c);
            const float so = fmaf(to, 0.5f, 0.5f);
            h = so * tc;

            op[(t0 + u) * OUTSTRIDE] = h;        // coalesced
        }

#pragma unroll
        for (int u = 0; u < UNROLL; ++u) xbuf[u] = xnxt[u];
    }
}

extern "C" void kernel_launch(void* const* d_in, const int* in_sizes, int n_in,
                              void* d_out, int out_size)
{
    const float* input = (const float*)d_in[0];
    const float* W_ih  = (const float*)d_in[1];
    const float* W_hh  = (const float*)d_in[2];
    const float* b_ih  = (const float*)d_in[3];
    const float* b_hh  = (const float*)d_in[4];
    float* out = (float*)d_out;

    lstm_recur<<<128, 32>>>(input, W_ih, W_hh, b_ih, b_hh, out);
}